// round 14
// baseline (speedup 1.0000x reference)
#include <cuda_runtime.h>
#include <math.h>

#define NP 4096
#define NI 256
#define NH 64
#define NA 32

#define NBINS 512
#define TROWS (NBINS + 1)        // rows 0..512
#define PADOFF (TROWS * 128)     // byte offset of zero row

#define WPC 28                   // persons per CTA (2 per warp)
#define NWARP 14
#define NTHR (NWARP * 32)        // 448
#define GRID ((NP + WPC - 1) / WPC)   // 147

// Output layout (flattened tuple, fp32)
#define O_AMU  (NP * NI)
#define O_ALV  (O_AMU + NP * NA)
#define O_IMU  (O_ALV + NP * NA)
#define O_ILV  (O_IMU + NI)

// ---- staged block (word offsets) ----
#define TAB_WORDS ((TROWS + 1) * 32)      // 16448 (incl zero row)
#define TAB_BYTES (TAB_WORDS * 4)         // 65792
#define WSTRIDE 68
#define W3A_OFF TAB_WORDS
#define W3B_OFF (W3A_OFF + 32 * WSTRIDE)
#define W4A_OFF (W3B_OFF + 32 * WSTRIDE)
#define W4B_OFF (W4A_OFF + 32 * WSTRIDE)
#define IFE_OFF (W4B_OFF + 32 * WSTRIDE)
#define STAGED_WORDS (IFE_OFF + NI)       // 25408
#define STAGED_BYTES (STAGED_WORDS * 4)   // 101632
#define CHUNK2_BYTES (STAGED_BYTES - TAB_BYTES)

// smem: staged | cmp[WPC][264] | buf[WPC][64] | 2 mbars
#define CMP_STRIDE 264
#define CMP_OFF  STAGED_WORDS
#define BUF_OFF  (CMP_OFF + WPC * CMP_STRIDE)
#define MBAR_OFF (BUF_OFF + WPC * NH)
#define SMEM_BYTES (MBAR_OFF * 4 + 32)

__device__ __align__(16) float g_staged[STAGED_WORDS];

__device__ __forceinline__ float elu_ref(float x) {
    return x > 0.0f ? x : expm1f(x);
}
__device__ __forceinline__ float elu_fast(float x) {
    return x > 0.0f ? x : (__expf(x) - 1.0f);
}
__device__ __forceinline__ void addbf2(unsigned long long& acc, unsigned int w) {
    asm("{\n\t"
        ".reg .b32 lo, hi;\n\t"
        ".reg .b64 t;\n\t"
        "shl.b32 lo, %1, 16;\n\t"
        "and.b32 hi, %1, 0xffff0000;\n\t"
        "mov.b64 t, {lo, hi};\n\t"
        "add.rn.f32x2 %0, %0, t;\n\t"
        "}" : "+l"(acc) : "r"(w));
}
__device__ __forceinline__ void fma2(unsigned long long& acc,
                                     unsigned long long a, unsigned long long b) {
    asm("fma.rn.f32x2 %0, %1, %2, %0;" : "+l"(acc) : "l"(a), "l"(b));
}
__device__ __forceinline__ void mbar_wait(unsigned int mbar) {
    unsigned int done;
    asm volatile(
        "{\n\t.reg .pred p;\n\t"
        "mbarrier.try_wait.parity.acquire.cta.shared::cta.b64 p, [%1], 0;\n\t"
        "selp.b32 %0, 1, 0, p;\n\t}"
        : "=r"(done) : "r"(mbar) : "memory");
    while (!done) {
        asm volatile(
            "{\n\t.reg .pred p;\n\t"
            "mbarrier.try_wait.parity.acquire.cta.shared::cta.b64 p, [%1], 0, 0x989680;\n\t"
            "selp.b32 %0, 1, 0, p;\n\t}"
            : "=r"(done) : "r"(mbar) : "memory");
    }
}
#define PAIR_BAR(wid) \
    asm volatile("bar.sync %0, 64;" :: "r"(1 + ((wid) >> 1)) : "memory")

// ---------------------------------------------------------------------------
// Kernel 1: FAST builder (129 table blocks x 256 threads, w2 staged once).
// ---------------------------------------------------------------------------
#define TBLK ((TROWS + 3) / 4)   // 129

__global__ void build_all_kernel(const float* __restrict__ w1,
                                 const float* __restrict__ b1,
                                 const float* __restrict__ w2,
                                 const float* __restrict__ b2,
                                 const float* __restrict__ w3,
                                 const float* __restrict__ w4,
                                 const int*   __restrict__ item_index,
                                 const float* __restrict__ eps_item,
                                 const float* __restrict__ mu_table,
                                 const float* __restrict__ logvar_table,
                                 float* __restrict__ out) {
    int blk = blockIdx.x;
    int t = threadIdx.x;   // 0..255

    if (blk < TBLK) {
        __shared__ float w2s[NH * NH];
        __shared__ float sh1[4][NH];
        {
            const float4* src = (const float4*)w2;
            float4* dst = (float4*)w2s;
#pragma unroll
            for (int i = t; i < (NH * NH) / 4; i += 256) dst[i] = src[i];
        }
        const int r = t >> 6;
        const int j = t & 63;
        const int row = blk * 4 + r;
        {
            float x = (float)row * (1.0f / (float)NBINS);
            sh1[r][j] = elu_ref(fmaf(w1[j], x, b1[j]));
        }
        __syncthreads();
        if (row < TROWS) {
            float z0 = b2[j], z1 = 0.0f, z2 = 0.0f, z3 = 0.0f;
            const float* h1r = sh1[r];
#pragma unroll
            for (int k = 0; k < NH; k += 4) {
                z0 = fmaf(h1r[k],     w2s[k * NH + j],       z0);
                z1 = fmaf(h1r[k + 1], w2s[(k + 1) * NH + j], z1);
                z2 = fmaf(h1r[k + 2], w2s[(k + 2) * NH + j], z2);
                z3 = fmaf(h1r[k + 3], w2s[(k + 3) * NH + j], z3);
            }
            float z = elu_ref((z0 + z1) + (z2 + z3));
            float zo = __shfl_xor_sync(0xffffffffu, z, 1);
            if ((j & 1) == 0) {
                unsigned int u;
                asm("cvt.rn.bf16x2.f32 %0, %1, %2;" : "=r"(u) : "f"(zo), "f"(z));
                g_staged[row * 32 + (j >> 1)] = __uint_as_float(u);
            }
        }
    } else if (blk < TBLK + 4) {
        int arr = blk - TBLK;
        const float* src = (arr < 2) ? w3 : w4;
        int parity = arr & 1;
        int dst = W3A_OFF + arr * 32 * WSTRIDE;
#pragma unroll
        for (int i = t; i < 32 * NH; i += 256) {
            int k = i >> 5, l = i & 31;
            g_staged[dst + l * WSTRIDE + k] = src[k * NH + 2 * l + parity];
        }
    } else {
        if (t < 32) g_staged[TROWS * 32 + t] = 0.0f;
        if (t < NI) {
            int idx = item_index[t];
            float imu = mu_table[idx];
            float ilv = logvar_table[idx];
            g_staged[IFE_OFF + t] = fmaf(eps_item[t], __expf(0.5f * ilv), imu);
            out[O_IMU + t] = imu;
            out[O_ILV + t] = ilv;
        }
    }
}

// ---------------------------------------------------------------------------
// Kernel 2: 14 warps, 2 persons/warp; warp-pair shared layers (4 persons per
// weight load, even warp computes). No early returns (barrier safety).
// ---------------------------------------------------------------------------
__global__ __launch_bounds__(NTHR, 1)
void vibo_main_kernel(const float* __restrict__ response,
                      const int*   __restrict__ mask,
                      const float* __restrict__ eps_ability,
                      const float* __restrict__ b3,
                      const float* __restrict__ b4,
                      float* __restrict__ out) {
    extern __shared__ float sm[];
    const int tid = threadIdx.x;
    const int wid  = tid >> 5;
    const int lane = tid & 31;
    const int p0 = blockIdx.x * WPC + wid * 2;
    const int p1 = p0 + 1;

    unsigned int smb;
    asm("{ .reg .u64 t; cvta.to.shared.u64 t, %1; cvt.u32.u64 %0, t; }"
        : "=r"(smb) : "l"(sm));
    const unsigned int bar1 = smb + MBAR_OFF * 4;
    const unsigned int bar2 = bar1 + 8;

    // ---- early gmem loads (both persons) ----
    float4 r0a, r1a, r0b, r1b; int4 m0a, m1a, m0b, m1b;
    if (p0 < NP) {
        const float4* rp = (const float4*)(response + p0 * NI);
        const int4*   mp = (const int4*)(mask + p0 * NI);
        r0a = rp[lane * 2]; r1a = rp[lane * 2 + 1];
        m0a = mp[lane * 2]; m1a = mp[lane * 2 + 1];
    }
    if (p1 < NP) {
        const float4* rp = (const float4*)(response + p1 * NI);
        const int4*   mp = (const int4*)(mask + p1 * NI);
        r0b = rp[lane * 2]; r1b = rp[lane * 2 + 1];
        m0b = mp[lane * 2]; m1b = mp[lane * 2 + 1];
    }

    if (tid == 0) {
        asm volatile("mbarrier.init.shared.b64 [%0], 1;" :: "r"(bar1) : "memory");
        asm volatile("mbarrier.init.shared.b64 [%0], 1;" :: "r"(bar2) : "memory");
    }
    __syncthreads();
    if (tid == 0) {
        asm volatile("mbarrier.arrive.expect_tx.shared.b64 _, [%0], %1;"
                     :: "r"(bar1), "r"((unsigned)TAB_BYTES) : "memory");
        asm volatile("cp.async.bulk.shared::cluster.global.mbarrier::complete_tx::bytes "
                     "[%0], [%1], %2, [%3];"
                     :: "r"(smb), "l"((const void*)g_staged),
                        "r"((unsigned)TAB_BYTES), "r"(bar1) : "memory");
        asm volatile("mbarrier.arrive.expect_tx.shared.b64 _, [%0], %1;"
                     :: "r"(bar2), "r"((unsigned)CHUNK2_BYTES) : "memory");
        asm volatile("cp.async.bulk.shared::cluster.global.mbarrier::complete_tx::bytes "
                     "[%0], [%1], %2, [%3];"
                     :: "r"(smb + TAB_BYTES), "l"((const void*)(g_staged + TAB_WORDS)),
                        "r"((unsigned)CHUNK2_BYTES), "r"(bar2) : "memory");
    }

    // ---- compaction for both persons (overlaps TMA) ----
    unsigned int* cmp0 = (unsigned int*)(sm + CMP_OFF) + (wid * 2) * CMP_STRIDE;
    unsigned int* cmp1 = cmp0 + CMP_STRIDE;
    int tot0 = 0, tot1 = 0;
#pragma unroll
    for (int pp = 0; pp < 2; pp++) {
        int pv = pp ? p1 : p0;
        if (pv >= NP) continue;
        float4 rA = pp ? r0b : r0a, rB = pp ? r1b : r1a;
        int4   mA = pp ? m0b : m0a, mB = pp ? m1b : m1a;
        float rv[8] = {rA.x, rA.y, rA.z, rA.w, rB.x, rB.y, rB.z, rB.w};
        int   mv[8] = {mA.x, mA.y, mA.z, mA.w, mB.x, mB.y, mB.z, mB.w};
        int cnt = 0;
#pragma unroll
        for (int j = 0; j < 8; j++) cnt += (mv[j] != 0);
        int off = cnt;
#pragma unroll
        for (int d = 1; d < 32; d <<= 1) {
            int t = __shfl_up_sync(0xffffffffu, off, d);
            if (lane >= d) off += t;
        }
        int tot = __shfl_sync(0xffffffffu, off, 31);
        off -= cnt;
        unsigned int* cc = pp ? cmp1 : cmp0;
        int pos = off;
#pragma unroll
        for (int j = 0; j < 8; j++) {
            if (mv[j]) {
                int b = __float2int_rn(rv[j] * (float)NBINS);
                if (b < 0) b = 0;
                if (b > NBINS) b = NBINS;
                cc[pos++] = (unsigned int)(b << 7);
            }
        }
        if (pp) tot1 = tot; else tot0 = tot;
    }
    int tmax = max(tot0, tot1);
    int totalp = (tmax + 3) & ~3;
    for (int t = tot0 + lane; t < totalp + 4; t += 32) cmp0[t] = PADOFF;
    for (int t = tot1 + lane; t < totalp + 4; t += 32) cmp1[t] = PADOFF;
    __syncwarp();

    mbar_wait(bar1);

    // ---- NN accumulate, both persons, prefetched offsets ----
    const char* tb = (const char*)sm + lane * 4;
    const uint4* c0 = (const uint4*)cmp0;
    const uint4* c1 = (const uint4*)cmp1;
    unsigned long long a0 = 0ull, a1 = 0ull, a2 = 0ull, a3 = 0ull;
    const int n4 = totalp >> 2;
    uint4 oA4 = c0[0];
    uint4 oB4 = c1[0];
#pragma unroll 2
    for (int i = 0; i < n4; i++) {
        uint4 nA = c0[i + 1];
        uint4 nB = c1[i + 1];
        unsigned int vA0 = *(const unsigned int*)(tb + oA4.x);
        unsigned int vA1 = *(const unsigned int*)(tb + oA4.y);
        unsigned int vA2 = *(const unsigned int*)(tb + oA4.z);
        unsigned int vA3 = *(const unsigned int*)(tb + oA4.w);
        unsigned int vB0 = *(const unsigned int*)(tb + oB4.x);
        unsigned int vB1 = *(const unsigned int*)(tb + oB4.y);
        unsigned int vB2 = *(const unsigned int*)(tb + oB4.z);
        unsigned int vB3 = *(const unsigned int*)(tb + oB4.w);
        addbf2(a0, vA0); addbf2(a1, vA1);
        addbf2(a2, vB0); addbf2(a3, vB1);
        addbf2(a0, vA2); addbf2(a1, vA3);
        addbf2(a2, vB2); addbf2(a3, vB3);
        oA4 = nA; oB4 = nB;
    }
    asm("add.rn.f32x2 %0, %0, %1;" : "+l"(a0) : "l"(a1));
    asm("add.rn.f32x2 %0, %0, %1;" : "+l"(a2) : "l"(a3));
    float h0x, h0y, h1x, h1y;
    asm("mov.b64 {%0, %1}, %2;" : "=f"(h0x), "=f"(h0y) : "l"(a0));
    asm("mov.b64 {%0, %1}, %2;" : "=f"(h1x), "=f"(h1y) : "l"(a2));
    float inv0 = 1.0f / fmaxf((float)tot0, 1.0f);
    float inv1 = 1.0f / fmaxf((float)tot1, 1.0f);

    const int d0 = lane * 2;
    float* buf0 = sm + BUF_OFF + (wid * 2) * NH;
    float* buf1 = buf0 + NH;
    buf0[d0] = h0x * inv0; buf0[d0 + 1] = h0y * inv0;
    buf1[d0] = h1x * inv1; buf1[d0 + 1] = h1y * inv1;

    mbar_wait(bar2);
    PAIR_BAR(wid);    // pair's hm all visible

    float oA0, oA1, oB0, oB1;

    if ((wid & 1) == 0) {
        // ---- even warp: layers for 4 persons of the pair ----
        float* pb0 = sm + BUF_OFF + (wid * 2) * NH;   // own person 0
        float* pb1 = pb0 + NH;                         // own person 1
        float* pb2 = pb0 + 2 * NH;                     // odd warp person 0
        float* pb3 = pb0 + 3 * NH;                     // odd warp person 1
        const ulonglong2* hb0 = (const ulonglong2*)pb0;
        const ulonglong2* hb1 = (const ulonglong2*)pb1;
        const ulonglong2* hb2 = (const ulonglong2*)pb2;
        const ulonglong2* hb3 = (const ulonglong2*)pb3;
        const ulonglong2* wa3 = (const ulonglong2*)(sm + W3A_OFF + lane * WSTRIDE);
        const ulonglong2* wb3 = (const ulonglong2*)(sm + W3B_OFF + lane * WSTRIDE);

        unsigned long long zP0, zP1, zQ0, zQ1, zR0, zR1, zS0, zS1;
        {
            float bz = b3[d0], bz1 = b3[d0 + 1], zf = 0.0f;
            asm("mov.b64 %0, {%1, %2};" : "=l"(zP0) : "f"(bz),  "f"(zf));
            asm("mov.b64 %0, {%1, %2};" : "=l"(zP1) : "f"(bz1), "f"(zf));
            zQ0 = zP0; zQ1 = zP1; zR0 = zP0; zR1 = zP1; zS0 = zP0; zS1 = zP1;
        }
#pragma unroll
        for (int k4 = 0; k4 < NH / 4; k4++) {
            ulonglong2 hA = hb0[k4];
            ulonglong2 hB = hb1[k4];
            ulonglong2 hC = hb2[k4];
            ulonglong2 hD = hb3[k4];
            ulonglong2 wa = wa3[k4];
            ulonglong2 wb = wb3[k4];
            fma2(zP0, hA.x, wa.x); fma2(zP0, hA.y, wa.y);
            fma2(zP1, hA.x, wb.x); fma2(zP1, hA.y, wb.y);
            fma2(zQ0, hB.x, wa.x); fma2(zQ0, hB.y, wa.y);
            fma2(zQ1, hB.x, wb.x); fma2(zQ1, hB.y, wb.y);
            fma2(zR0, hC.x, wa.x); fma2(zR0, hC.y, wa.y);
            fma2(zR1, hC.x, wb.x); fma2(zR1, hC.y, wb.y);
            fma2(zS0, hD.x, wa.x); fma2(zS0, hD.y, wa.y);
            fma2(zS1, hD.x, wb.x); fma2(zS1, hD.y, wb.y);
        }
        float s0, s1, s2, s3;
        float uA0, uA1, uB0, uB1, uC0, uC1, uD0, uD1;
        asm("mov.b64 {%0, %1}, %2;" : "=f"(s0), "=f"(s1) : "l"(zP0));
        asm("mov.b64 {%0, %1}, %2;" : "=f"(s2), "=f"(s3) : "l"(zP1));
        uA0 = elu_fast(s0 + s1); uA1 = elu_fast(s2 + s3);
        asm("mov.b64 {%0, %1}, %2;" : "=f"(s0), "=f"(s1) : "l"(zQ0));
        asm("mov.b64 {%0, %1}, %2;" : "=f"(s2), "=f"(s3) : "l"(zQ1));
        uB0 = elu_fast(s0 + s1); uB1 = elu_fast(s2 + s3);
        asm("mov.b64 {%0, %1}, %2;" : "=f"(s0), "=f"(s1) : "l"(zR0));
        asm("mov.b64 {%0, %1}, %2;" : "=f"(s2), "=f"(s3) : "l"(zR1));
        uC0 = elu_fast(s0 + s1); uC1 = elu_fast(s2 + s3);
        asm("mov.b64 {%0, %1}, %2;" : "=f"(s0), "=f"(s1) : "l"(zS0));
        asm("mov.b64 {%0, %1}, %2;" : "=f"(s2), "=f"(s3) : "l"(zS1));
        uD0 = elu_fast(s0 + s1); uD1 = elu_fast(s2 + s3);
        __syncwarp();
        pb0[d0] = uA0; pb0[d0 + 1] = uA1;
        pb1[d0] = uB0; pb1[d0 + 1] = uB1;
        pb2[d0] = uC0; pb2[d0 + 1] = uC1;
        pb3[d0] = uD0; pb3[d0 + 1] = uD1;
        __syncwarp();

        const ulonglong2* wa4 = (const ulonglong2*)(sm + W4A_OFF + lane * WSTRIDE);
        const ulonglong2* wb4 = (const ulonglong2*)(sm + W4B_OFF + lane * WSTRIDE);
        {
            float bz = b4[d0], bz1 = b4[d0 + 1], zf = 0.0f;
            asm("mov.b64 %0, {%1, %2};" : "=l"(zP0) : "f"(bz),  "f"(zf));
            asm("mov.b64 %0, {%1, %2};" : "=l"(zP1) : "f"(bz1), "f"(zf));
            zQ0 = zP0; zQ1 = zP1; zR0 = zP0; zR1 = zP1; zS0 = zP0; zS1 = zP1;
        }
#pragma unroll
        for (int k4 = 0; k4 < NH / 4; k4++) {
            ulonglong2 hA = hb0[k4];
            ulonglong2 hB = hb1[k4];
            ulonglong2 hC = hb2[k4];
            ulonglong2 hD = hb3[k4];
            ulonglong2 wa = wa4[k4];
            ulonglong2 wb = wb4[k4];
            fma2(zP0, hA.x, wa.x); fma2(zP0, hA.y, wa.y);
            fma2(zP1, hA.x, wb.x); fma2(zP1, hA.y, wb.y);
            fma2(zQ0, hB.x, wa.x); fma2(zQ0, hB.y, wa.y);
            fma2(zQ1, hB.x, wb.x); fma2(zQ1, hB.y, wb.y);
            fma2(zR0, hC.x, wa.x); fma2(zR0, hC.y, wa.y);
            fma2(zR1, hC.x, wb.x); fma2(zR1, hC.y, wb.y);
            fma2(zS0, hD.x, wa.x); fma2(zS0, hD.y, wa.y);
            fma2(zS1, hD.x, wb.x); fma2(zS1, hD.y, wb.y);
        }
        asm("mov.b64 {%0, %1}, %2;" : "=f"(s0), "=f"(s1) : "l"(zP0));
        asm("mov.b64 {%0, %1}, %2;" : "=f"(s2), "=f"(s3) : "l"(zP1));
        oA0 = s0 + s1; oA1 = s2 + s3;
        asm("mov.b64 {%0, %1}, %2;" : "=f"(s0), "=f"(s1) : "l"(zQ0));
        asm("mov.b64 {%0, %1}, %2;" : "=f"(s2), "=f"(s3) : "l"(zQ1));
        oB0 = s0 + s1; oB1 = s2 + s3;
        float oC0, oC1, oD0, oD1;
        asm("mov.b64 {%0, %1}, %2;" : "=f"(s0), "=f"(s1) : "l"(zR0));
        asm("mov.b64 {%0, %1}, %2;" : "=f"(s2), "=f"(s3) : "l"(zR1));
        oC0 = s0 + s1; oC1 = s2 + s3;
        asm("mov.b64 {%0, %1}, %2;" : "=f"(s0), "=f"(s1) : "l"(zS0));
        asm("mov.b64 {%0, %1}, %2;" : "=f"(s2), "=f"(s3) : "l"(zS1));
        oD0 = s0 + s1; oD1 = s2 + s3;
        __syncwarp();
        pb2[d0] = oC0; pb2[d0 + 1] = oC1;    // hand odd warp its outputs
        pb3[d0] = oD0; pb3[d0 + 1] = oD1;
    }
    PAIR_BAR(wid);
    if (wid & 1) {
        float* ob0 = sm + BUF_OFF + (wid * 2) * NH;
        float* ob1 = ob0 + NH;
        oA0 = ob0[d0]; oA1 = ob0[d0 + 1];
        oB0 = ob1[d0]; oB1 = ob1[d0 + 1];
    }

    // ---- epilogue per person ----
#pragma unroll
    for (int pp = 0; pp < 2; pp++) {
        int p = pp ? p1 : p0;
        if (p >= NP) break;
        float o0 = pp ? oB0 : oA0;
        float o1 = pp ? oB1 : oA1;
        float2 ov = make_float2(o0, o1);
        if (lane < 16) *(float2*)&out[O_AMU + p * NA + d0] = ov;
        else           *(float2*)&out[O_ALV + p * NA + (d0 - NA)] = ov;

        float lv0 = __shfl_down_sync(0xffffffffu, o0, 16);
        float lv1 = __shfl_down_sync(0xffffffffu, o1, 16);
        float term = 0.0f;
        if (lane < 16) {
            float2 eps = *(const float2*)&eps_ability[p * NA + d0];
            term = o0 + eps.x * __expf(0.5f * lv0)
                 + o1 + eps.y * __expf(0.5f * lv1);
        }
#pragma unroll
        for (int w = 16; w > 0; w >>= 1)
            term += __shfl_xor_sync(0xffffffffu, term, w);
        float asum = term;

        const float4* ifp = (const float4*)(sm + IFE_OFF + lane * 8);
        float4* orow = (float4*)(out + p * NI + lane * 8);
#pragma unroll
        for (int v = 0; v < 2; v++) {
            float4 f = ifp[v];
            float4 r;
            r.x = __fdividef(1.0f, 1.0f + __expf(-(asum + f.x)));
            r.y = __fdividef(1.0f, 1.0f + __expf(-(asum + f.y)));
            r.z = __fdividef(1.0f, 1.0f + __expf(-(asum + f.z)));
            r.w = __fdividef(1.0f, 1.0f + __expf(-(asum + f.w)));
            orow[v] = r;
        }
    }
}

// ---------------------------------------------------------------------------
extern "C" void kernel_launch(void* const* d_in, const int* in_sizes, int n_in,
                              void* d_out, int out_size) {
    const float* response     = (const float*)d_in[0];
    const int*   mask         = (const int*)  d_in[1];
    const int*   item_index   = (const int*)  d_in[2];
    const float* eps_ability  = (const float*)d_in[3];
    const float* eps_item     = (const float*)d_in[4];
    const float* w1           = (const float*)d_in[5];
    const float* b1           = (const float*)d_in[6];
    const float* w2           = (const float*)d_in[7];
    const float* b2           = (const float*)d_in[8];
    const float* w3           = (const float*)d_in[9];
    const float* b3           = (const float*)d_in[10];
    const float* w4           = (const float*)d_in[11];
    const float* b4           = (const float*)d_in[12];
    const float* mu_table     = (const float*)d_in[13];
    const float* logvar_table = (const float*)d_in[14];
    float* out = (float*)d_out;

    cudaFuncSetAttribute(vibo_main_kernel,
                         cudaFuncAttributeMaxDynamicSharedMemorySize, SMEM_BYTES);

    build_all_kernel<<<TBLK + 5, 256>>>(w1, b1, w2, b2, w3, w4,
                                        item_index, eps_item,
                                        mu_table, logvar_table, out);

    vibo_main_kernel<<<GRID, NTHR, SMEM_BYTES>>>(response, mask,
                                                 eps_ability, b3, b4, out);
}

// round 15
// speedup vs baseline: 1.0332x; 1.0332x over previous
#include <cuda_runtime.h>
#include <math.h>

#define NP 4096
#define NI 256
#define NH 64
#define NA 32

#define NBINS 512
#define TROWS (NBINS + 1)        // rows 0..512
#define PADOFF (TROWS * 128)     // byte offset of zero row

#define NWARP 28                 // 1 person per warp; pairs share layer weights
#define WPC NWARP                // 28 persons per CTA
#define NTHR (NWARP * 32)        // 896
#define GRID ((NP + WPC - 1) / WPC)   // 147

// Output layout (flattened tuple, fp32)
#define O_AMU  (NP * NI)
#define O_ALV  (O_AMU + NP * NA)
#define O_IMU  (O_ALV + NP * NA)
#define O_ILV  (O_IMU + NI)

// ---- staged block (word offsets) ----
#define TAB_WORDS ((TROWS + 1) * 32)      // 16448 (incl zero row)
#define TAB_BYTES (TAB_WORDS * 4)         // 65792
#define WSTRIDE 68
#define W3A_OFF TAB_WORDS
#define W3B_OFF (W3A_OFF + 32 * WSTRIDE)
#define W4A_OFF (W3B_OFF + 32 * WSTRIDE)
#define W4B_OFF (W4A_OFF + 32 * WSTRIDE)
#define IFE_OFF (W4B_OFF + 32 * WSTRIDE)
#define STAGED_WORDS (IFE_OFF + NI)       // 25408
#define STAGED_BYTES (STAGED_WORDS * 4)   // 101632
#define CHUNK2_BYTES (STAGED_BYTES - TAB_BYTES)

// smem: staged | cmp[28][264] | buf[28][64] | 2 mbars  (~138 KB, 1 CTA/SM)
#define CMP_STRIDE 264
#define CMP_OFF  STAGED_WORDS
#define BUF_OFF  (CMP_OFF + WPC * CMP_STRIDE)
#define MBAR_OFF (BUF_OFF + WPC * NH)
#define SMEM_BYTES (MBAR_OFF * 4 + 32)

__device__ __align__(16) float g_staged[STAGED_WORDS];

__device__ __forceinline__ float elu_ref(float x) {
    return x > 0.0f ? x : expm1f(x);
}
__device__ __forceinline__ float elu_fast(float x) {
    return x > 0.0f ? x : (__expf(x) - 1.0f);
}
__device__ __forceinline__ void addbf2(unsigned long long& acc, unsigned int w) {
    asm("{\n\t"
        ".reg .b32 lo, hi;\n\t"
        ".reg .b64 t;\n\t"
        "shl.b32 lo, %1, 16;\n\t"
        "and.b32 hi, %1, 0xffff0000;\n\t"
        "mov.b64 t, {lo, hi};\n\t"
        "add.rn.f32x2 %0, %0, t;\n\t"
        "}" : "+l"(acc) : "r"(w));
}
__device__ __forceinline__ void fma2(unsigned long long& acc,
                                     unsigned long long a, unsigned long long b) {
    asm("fma.rn.f32x2 %0, %1, %2, %0;" : "+l"(acc) : "l"(a), "l"(b));
}
__device__ __forceinline__ void mbar_wait(unsigned int mbar) {
    unsigned int done;
    asm volatile(
        "{\n\t.reg .pred p;\n\t"
        "mbarrier.try_wait.parity.acquire.cta.shared::cta.b64 p, [%1], 0;\n\t"
        "selp.b32 %0, 1, 0, p;\n\t}"
        : "=r"(done) : "r"(mbar) : "memory");
    while (!done) {
        asm volatile(
            "{\n\t.reg .pred p;\n\t"
            "mbarrier.try_wait.parity.acquire.cta.shared::cta.b64 p, [%1], 0, 0x989680;\n\t"
            "selp.b32 %0, 1, 0, p;\n\t}"
            : "=r"(done) : "r"(mbar) : "memory");
    }
}
#define PAIR_BAR(wid) \
    asm volatile("bar.sync %0, 64;" :: "r"(1 + ((wid) >> 1)) : "memory")

// ---------------------------------------------------------------------------
// Kernel 1: FAST builder (129 table blocks x 256 threads, w2 staged once).
// ---------------------------------------------------------------------------
#define TBLK ((TROWS + 3) / 4)   // 129

__global__ void build_all_kernel(const float* __restrict__ w1,
                                 const float* __restrict__ b1,
                                 const float* __restrict__ w2,
                                 const float* __restrict__ b2,
                                 const float* __restrict__ w3,
                                 const float* __restrict__ w4,
                                 const int*   __restrict__ item_index,
                                 const float* __restrict__ eps_item,
                                 const float* __restrict__ mu_table,
                                 const float* __restrict__ logvar_table,
                                 float* __restrict__ out) {
    int blk = blockIdx.x;
    int t = threadIdx.x;   // 0..255

    if (blk < TBLK) {
        __shared__ float w2s[NH * NH];
        __shared__ float sh1[4][NH];
        {
            const float4* src = (const float4*)w2;
            float4* dst = (float4*)w2s;
#pragma unroll
            for (int i = t; i < (NH * NH) / 4; i += 256) dst[i] = src[i];
        }
        const int r = t >> 6;
        const int j = t & 63;
        const int row = blk * 4 + r;
        {
            float x = (float)row * (1.0f / (float)NBINS);
            sh1[r][j] = elu_ref(fmaf(w1[j], x, b1[j]));
        }
        __syncthreads();
        if (row < TROWS) {
            float z0 = b2[j], z1 = 0.0f, z2 = 0.0f, z3 = 0.0f;
            const float* h1r = sh1[r];
#pragma unroll
            for (int k = 0; k < NH; k += 4) {
                z0 = fmaf(h1r[k],     w2s[k * NH + j],       z0);
                z1 = fmaf(h1r[k + 1], w2s[(k + 1) * NH + j], z1);
                z2 = fmaf(h1r[k + 2], w2s[(k + 2) * NH + j], z2);
                z3 = fmaf(h1r[k + 3], w2s[(k + 3) * NH + j], z3);
            }
            float z = elu_ref((z0 + z1) + (z2 + z3));
            float zo = __shfl_xor_sync(0xffffffffu, z, 1);
            if ((j & 1) == 0) {
                unsigned int u;
                asm("cvt.rn.bf16x2.f32 %0, %1, %2;" : "=r"(u) : "f"(zo), "f"(z));
                g_staged[row * 32 + (j >> 1)] = __uint_as_float(u);
            }
        }
    } else if (blk < TBLK + 4) {
        int arr = blk - TBLK;
        const float* src = (arr < 2) ? w3 : w4;
        int parity = arr & 1;
        int dst = W3A_OFF + arr * 32 * WSTRIDE;
#pragma unroll
        for (int i = t; i < 32 * NH; i += 256) {
            int k = i >> 5, l = i & 31;
            g_staged[dst + l * WSTRIDE + k] = src[k * NH + 2 * l + parity];
        }
    } else {
        if (t < 32) g_staged[TROWS * 32 + t] = 0.0f;
        if (t < NI) {
            int idx = item_index[t];
            float imu = mu_table[idx];
            float ilv = logvar_table[idx];
            g_staged[IFE_OFF + t] = fmaf(eps_item[t], __expf(0.5f * ilv), imu);
            out[O_IMU + t] = imu;
            out[O_ILV + t] = ilv;
        }
    }
}

// ---------------------------------------------------------------------------
// Kernel 2: 28 warps, 1 person/warp (2x latency hiding in the main loop);
// even warps run both layer passes for the pair (weights loaded once per 2
// persons). No early returns — all warps reach the pair barriers.
// ---------------------------------------------------------------------------
__global__ __launch_bounds__(NTHR, 1)
void vibo_main_kernel(const float* __restrict__ response,
                      const int*   __restrict__ mask,
                      const float* __restrict__ eps_ability,
                      const float* __restrict__ b3,
                      const float* __restrict__ b4,
                      float* __restrict__ out) {
    extern __shared__ float sm[];
    const int tid = threadIdx.x;
    const int wid  = tid >> 5;
    const int lane = tid & 31;
    const int p = blockIdx.x * WPC + wid;

    unsigned int smb;
    asm("{ .reg .u64 t; cvta.to.shared.u64 t, %1; cvt.u32.u64 %0, t; }"
        : "=r"(smb) : "l"(sm));
    const unsigned int bar1 = smb + MBAR_OFF * 4;
    const unsigned int bar2 = bar1 + 8;

    // ---- early gmem loads (own person) ----
    float4 r0, r1; int4 m0, m1;
    if (p < NP) {
        const float4* rp = (const float4*)(response + p * NI);
        const int4*   mp = (const int4*)(mask + p * NI);
        r0 = rp[lane * 2]; r1 = rp[lane * 2 + 1];
        m0 = mp[lane * 2]; m1 = mp[lane * 2 + 1];
    }

    if (tid == 0) {
        asm volatile("mbarrier.init.shared.b64 [%0], 1;" :: "r"(bar1) : "memory");
        asm volatile("mbarrier.init.shared.b64 [%0], 1;" :: "r"(bar2) : "memory");
    }
    __syncthreads();
    if (tid == 0) {
        asm volatile("mbarrier.arrive.expect_tx.shared.b64 _, [%0], %1;"
                     :: "r"(bar1), "r"((unsigned)TAB_BYTES) : "memory");
        asm volatile("cp.async.bulk.shared::cluster.global.mbarrier::complete_tx::bytes "
                     "[%0], [%1], %2, [%3];"
                     :: "r"(smb), "l"((const void*)g_staged),
                        "r"((unsigned)TAB_BYTES), "r"(bar1) : "memory");
        asm volatile("mbarrier.arrive.expect_tx.shared.b64 _, [%0], %1;"
                     :: "r"(bar2), "r"((unsigned)CHUNK2_BYTES) : "memory");
        asm volatile("cp.async.bulk.shared::cluster.global.mbarrier::complete_tx::bytes "
                     "[%0], [%1], %2, [%3];"
                     :: "r"(smb + TAB_BYTES), "l"((const void*)(g_staged + TAB_WORDS)),
                        "r"((unsigned)CHUNK2_BYTES), "r"(bar2) : "memory");
    }

    // ---- compaction (own person; overlaps TMA) ----
    unsigned int* cmp = (unsigned int*)(sm + CMP_OFF) + wid * CMP_STRIDE;
    int total = 0;
    if (p < NP) {
        float rv[8] = {r0.x, r0.y, r0.z, r0.w, r1.x, r1.y, r1.z, r1.w};
        int   mv[8] = {m0.x, m0.y, m0.z, m0.w, m1.x, m1.y, m1.z, m1.w};
        int cnt = 0;
#pragma unroll
        for (int j = 0; j < 8; j++) cnt += (mv[j] != 0);
        int off = cnt;
#pragma unroll
        for (int d = 1; d < 32; d <<= 1) {
            int t = __shfl_up_sync(0xffffffffu, off, d);
            if (lane >= d) off += t;
        }
        total = __shfl_sync(0xffffffffu, off, 31);
        off -= cnt;
        int pos = off;
#pragma unroll
        for (int j = 0; j < 8; j++) {
            if (mv[j]) {
                int b = __float2int_rn(rv[j] * (float)NBINS);
                if (b < 0) b = 0;
                if (b > NBINS) b = NBINS;
                cmp[pos++] = (unsigned int)(b << 7);
            }
        }
    }
    int totalp = (total + 3) & ~3;
    for (int t = total + lane; t < totalp + 4; t += 32) cmp[t] = PADOFF;
    __syncwarp();

    mbar_wait(bar1);

    // ---- NN accumulate (own person), prefetched offsets ----
    const char* tb = (const char*)sm + lane * 4;
    const uint4* cw4 = (const uint4*)cmp;
    unsigned long long a0 = 0ull, a1 = 0ull;
    const int n4 = totalp >> 2;
    uint4 o4 = cw4[0];
#pragma unroll 2
    for (int i = 0; i < n4; i++) {
        uint4 nx = cw4[i + 1];     // padded: always safe
        unsigned int v0 = *(const unsigned int*)(tb + o4.x);
        unsigned int v1 = *(const unsigned int*)(tb + o4.y);
        unsigned int v2 = *(const unsigned int*)(tb + o4.z);
        unsigned int v3 = *(const unsigned int*)(tb + o4.w);
        addbf2(a0, v0);
        addbf2(a1, v1);
        addbf2(a0, v2);
        addbf2(a1, v3);
        o4 = nx;
    }
    asm("add.rn.f32x2 %0, %0, %1;" : "+l"(a0) : "l"(a1));
    float hx, hy;
    asm("mov.b64 {%0, %1}, %2;" : "=f"(hx), "=f"(hy) : "l"(a0));
    float inv = 1.0f / fmaxf((float)total, 1.0f);

    const int d0 = lane * 2;
    float* bufw = sm + BUF_OFF + wid * NH;
    bufw[d0]     = hx * inv;
    bufw[d0 + 1] = hy * inv;

    mbar_wait(bar2);
    PAIR_BAR(wid);                // pair's hm visible

    float o0, o1;                 // this warp's person's outputs

    if ((wid & 1) == 0) {
        // ---- even warp: layers for both persons of the pair ----
        float* pb0 = sm + BUF_OFF + wid * NH;        // own person
        float* pb1 = pb0 + NH;                        // odd warp's person
        const ulonglong2* hb0 = (const ulonglong2*)pb0;
        const ulonglong2* hb1 = (const ulonglong2*)pb1;
        const ulonglong2* wa3 = (const ulonglong2*)(sm + W3A_OFF + lane * WSTRIDE);
        const ulonglong2* wb3 = (const ulonglong2*)(sm + W3B_OFF + lane * WSTRIDE);
        unsigned long long zP0, zP1, zQ0, zQ1;
        {
            float bz = b3[d0], bz1 = b3[d0 + 1], zf = 0.0f;
            asm("mov.b64 %0, {%1, %2};" : "=l"(zP0) : "f"(bz),  "f"(zf));
            asm("mov.b64 %0, {%1, %2};" : "=l"(zP1) : "f"(bz1), "f"(zf));
            zQ0 = zP0; zQ1 = zP1;
        }
#pragma unroll
        for (int k4 = 0; k4 < NH / 4; k4++) {
            ulonglong2 hA = hb0[k4];
            ulonglong2 hB = hb1[k4];
            ulonglong2 wa = wa3[k4];
            ulonglong2 wb = wb3[k4];
            fma2(zP0, hA.x, wa.x); fma2(zP0, hA.y, wa.y);
            fma2(zP1, hA.x, wb.x); fma2(zP1, hA.y, wb.y);
            fma2(zQ0, hB.x, wa.x); fma2(zQ0, hB.y, wa.y);
            fma2(zQ1, hB.x, wb.x); fma2(zQ1, hB.y, wb.y);
        }
        float s0, s1, s2, s3;
        asm("mov.b64 {%0, %1}, %2;" : "=f"(s0), "=f"(s1) : "l"(zP0));
        asm("mov.b64 {%0, %1}, %2;" : "=f"(s2), "=f"(s3) : "l"(zP1));
        float uA0 = elu_fast(s0 + s1), uA1 = elu_fast(s2 + s3);
        asm("mov.b64 {%0, %1}, %2;" : "=f"(s0), "=f"(s1) : "l"(zQ0));
        asm("mov.b64 {%0, %1}, %2;" : "=f"(s2), "=f"(s3) : "l"(zQ1));
        float uB0 = elu_fast(s0 + s1), uB1 = elu_fast(s2 + s3);
        __syncwarp();
        pb0[d0] = uA0; pb0[d0 + 1] = uA1;
        pb1[d0] = uB0; pb1[d0 + 1] = uB1;
        __syncwarp();

        const ulonglong2* wa4 = (const ulonglong2*)(sm + W4A_OFF + lane * WSTRIDE);
        const ulonglong2* wb4 = (const ulonglong2*)(sm + W4B_OFF + lane * WSTRIDE);
        {
            float bz = b4[d0], bz1 = b4[d0 + 1], zf = 0.0f;
            asm("mov.b64 %0, {%1, %2};" : "=l"(zP0) : "f"(bz),  "f"(zf));
            asm("mov.b64 %0, {%1, %2};" : "=l"(zP1) : "f"(bz1), "f"(zf));
            zQ0 = zP0; zQ1 = zP1;
        }
#pragma unroll
        for (int k4 = 0; k4 < NH / 4; k4++) {
            ulonglong2 hA = hb0[k4];
            ulonglong2 hB = hb1[k4];
            ulonglong2 wa = wa4[k4];
            ulonglong2 wb = wb4[k4];
            fma2(zP0, hA.x, wa.x); fma2(zP0, hA.y, wa.y);
            fma2(zP1, hA.x, wb.x); fma2(zP1, hA.y, wb.y);
            fma2(zQ0, hB.x, wa.x); fma2(zQ0, hB.y, wa.y);
            fma2(zQ1, hB.x, wb.x); fma2(zQ1, hB.y, wb.y);
        }
        asm("mov.b64 {%0, %1}, %2;" : "=f"(s0), "=f"(s1) : "l"(zP0));
        asm("mov.b64 {%0, %1}, %2;" : "=f"(s2), "=f"(s3) : "l"(zP1));
        o0 = s0 + s1; o1 = s2 + s3;                  // own person
        float oB0, oB1;
        asm("mov.b64 {%0, %1}, %2;" : "=f"(s0), "=f"(s1) : "l"(zQ0));
        asm("mov.b64 {%0, %1}, %2;" : "=f"(s2), "=f"(s3) : "l"(zQ1));
        oB0 = s0 + s1; oB1 = s2 + s3;
        __syncwarp();
        pb1[d0] = oB0; pb1[d0 + 1] = oB1;            // hand odd its outputs
    }
    PAIR_BAR(wid);
    if (wid & 1) {
        float* ob = sm + BUF_OFF + wid * NH;
        o0 = ob[d0]; o1 = ob[d0 + 1];
    }

    // ---- epilogue (own person) ----
    if (p < NP) {
        float2 ov = make_float2(o0, o1);
        if (lane < 16) *(float2*)&out[O_AMU + p * NA + d0] = ov;
        else           *(float2*)&out[O_ALV + p * NA + (d0 - NA)] = ov;

        float lv0 = __shfl_down_sync(0xffffffffu, o0, 16);
        float lv1 = __shfl_down_sync(0xffffffffu, o1, 16);
        float term = 0.0f;
        if (lane < 16) {
            float2 eps = *(const float2*)&eps_ability[p * NA + d0];
            term = o0 + eps.x * __expf(0.5f * lv0)
                 + o1 + eps.y * __expf(0.5f * lv1);
        }
#pragma unroll
        for (int w = 16; w > 0; w >>= 1)
            term += __shfl_xor_sync(0xffffffffu, term, w);
        float asum = term;

        const float4* ifp = (const float4*)(sm + IFE_OFF + lane * 8);
        float4* orow = (float4*)(out + p * NI + lane * 8);
#pragma unroll
        for (int v = 0; v < 2; v++) {
            float4 f = ifp[v];
            float4 r;
            r.x = __fdividef(1.0f, 1.0f + __expf(-(asum + f.x)));
            r.y = __fdividef(1.0f, 1.0f + __expf(-(asum + f.y)));
            r.z = __fdividef(1.0f, 1.0f + __expf(-(asum + f.z)));
            r.w = __fdividef(1.0f, 1.0f + __expf(-(asum + f.w)));
            orow[v] = r;
        }
    }
}

// ---------------------------------------------------------------------------
extern "C" void kernel_launch(void* const* d_in, const int* in_sizes, int n_in,
                              void* d_out, int out_size) {
    const float* response     = (const float*)d_in[0];
    const int*   mask         = (const int*)  d_in[1];
    const int*   item_index   = (const int*)  d_in[2];
    const float* eps_ability  = (const float*)d_in[3];
    const float* eps_item     = (const float*)d_in[4];
    const float* w1           = (const float*)d_in[5];
    const float* b1           = (const float*)d_in[6];
    const float* w2           = (const float*)d_in[7];
    const float* b2           = (const float*)d_in[8];
    const float* w3           = (const float*)d_in[9];
    const float* b3           = (const float*)d_in[10];
    const float* w4           = (const float*)d_in[11];
    const float* b4           = (const float*)d_in[12];
    const float* mu_table     = (const float*)d_in[13];
    const float* logvar_table = (const float*)d_in[14];
    float* out = (float*)d_out;

    cudaFuncSetAttribute(vibo_main_kernel,
                         cudaFuncAttributeMaxDynamicSharedMemorySize, SMEM_BYTES);

    build_all_kernel<<<TBLK + 5, 256>>>(w1, b1, w2, b2, w3, w4,
                                        item_index, eps_item,
                                        mu_table, logvar_table, out);

    vibo_main_kernel<<<GRID, NTHR, SMEM_BYTES>>>(response, mask,
                                                 eps_ability, b3, b4, out);
}

// round 16
// speedup vs baseline: 1.1193x; 1.0833x over previous
#include <cuda_runtime.h>
#include <math.h>

#define NP 4096
#define NI 256
#define NH 64
#define NA 32

#define NBINS 512
#define TROWS (NBINS + 1)        // rows 0..512
#define PADOFF (TROWS * 128)     // byte offset of zero row

#define WPC 28                   // persons per CTA (2 per warp)
#define NWARP 14
#define NTHR (NWARP * 32)        // 448
#define GRID ((NP + WPC - 1) / WPC)   // 147

// Output layout (flattened tuple, fp32)
#define O_AMU  (NP * NI)
#define O_ALV  (O_AMU + NP * NA)
#define O_IMU  (O_ALV + NP * NA)
#define O_ILV  (O_IMU + NI)

// ---- staged block (word offsets) ----
#define TAB_WORDS ((TROWS + 1) * 32)      // 16448 (incl zero row)
#define TAB_BYTES (TAB_WORDS * 4)         // 65792
#define WSTRIDE 68
#define W3A_OFF TAB_WORDS
#define W3B_OFF (W3A_OFF + 32 * WSTRIDE)
#define W4A_OFF (W3B_OFF + 32 * WSTRIDE)
#define W4B_OFF (W4A_OFF + 32 * WSTRIDE)
#define IFE_OFF (W4B_OFF + 32 * WSTRIDE)
#define STAGED_WORDS (IFE_OFF + NI)       // 25408
#define STAGED_BYTES (STAGED_WORDS * 4)   // 101632
#define CHUNK2_BYTES (STAGED_BYTES - TAB_BYTES)

// smem: staged | cmp[WPC][264] | buf[WPC][64] | 2 mbars
#define CMP_STRIDE 264
#define CMP_OFF  STAGED_WORDS
#define BUF_OFF  (CMP_OFF + WPC * CMP_STRIDE)
#define MBAR_OFF (BUF_OFF + WPC * NH)
#define SMEM_BYTES (MBAR_OFF * 4 + 32)

__device__ __align__(16) float g_staged[STAGED_WORDS];

__device__ __forceinline__ float elu_ref(float x) {
    return x > 0.0f ? x : expm1f(x);
}
__device__ __forceinline__ float elu_fast(float x) {
    return x > 0.0f ? x : (__expf(x) - 1.0f);
}
// bf16x2 word -> two scalar FADDs (bit-identical to packed f32x2 add)
__device__ __forceinline__ void addbf_s(float& accLo, float& accHi, unsigned int w) {
    accLo += __uint_as_float(w << 16);
    accHi += __uint_as_float(w & 0xffff0000u);
}
__device__ __forceinline__ void fma2(unsigned long long& acc,
                                     unsigned long long a, unsigned long long b) {
    asm("fma.rn.f32x2 %0, %1, %2, %0;" : "+l"(acc) : "l"(a), "l"(b));
}
__device__ __forceinline__ void mbar_wait(unsigned int mbar) {
    unsigned int done;
    asm volatile(
        "{\n\t.reg .pred p;\n\t"
        "mbarrier.try_wait.parity.acquire.cta.shared::cta.b64 p, [%1], 0;\n\t"
        "selp.b32 %0, 1, 0, p;\n\t}"
        : "=r"(done) : "r"(mbar) : "memory");
    while (!done) {
        asm volatile(
            "{\n\t.reg .pred p;\n\t"
            "mbarrier.try_wait.parity.acquire.cta.shared::cta.b64 p, [%1], 0, 0x989680;\n\t"
            "selp.b32 %0, 1, 0, p;\n\t}"
            : "=r"(done) : "r"(mbar) : "memory");
    }
}

// ---------------------------------------------------------------------------
// Kernel 1: FAST builder (129 table blocks x 256 threads, w2 staged once).
// ---------------------------------------------------------------------------
#define TBLK ((TROWS + 3) / 4)   // 129

__global__ void build_all_kernel(const float* __restrict__ w1,
                                 const float* __restrict__ b1,
                                 const float* __restrict__ w2,
                                 const float* __restrict__ b2,
                                 const float* __restrict__ w3,
                                 const float* __restrict__ w4,
                                 const int*   __restrict__ item_index,
                                 const float* __restrict__ eps_item,
                                 const float* __restrict__ mu_table,
                                 const float* __restrict__ logvar_table,
                                 float* __restrict__ out) {
    int blk = blockIdx.x;
    int t = threadIdx.x;   // 0..255

    if (blk < TBLK) {
        __shared__ float w2s[NH * NH];
        __shared__ float sh1[4][NH];
        {
            const float4* src = (const float4*)w2;
            float4* dst = (float4*)w2s;
#pragma unroll
            for (int i = t; i < (NH * NH) / 4; i += 256) dst[i] = src[i];
        }
        const int r = t >> 6;
        const int j = t & 63;
        const int row = blk * 4 + r;
        {
            float x = (float)row * (1.0f / (float)NBINS);
            sh1[r][j] = elu_ref(fmaf(w1[j], x, b1[j]));
        }
        __syncthreads();
        if (row < TROWS) {
            float z0 = b2[j], z1 = 0.0f, z2 = 0.0f, z3 = 0.0f;
            const float* h1r = sh1[r];
#pragma unroll
            for (int k = 0; k < NH; k += 4) {
                z0 = fmaf(h1r[k],     w2s[k * NH + j],       z0);
                z1 = fmaf(h1r[k + 1], w2s[(k + 1) * NH + j], z1);
                z2 = fmaf(h1r[k + 2], w2s[(k + 2) * NH + j], z2);
                z3 = fmaf(h1r[k + 3], w2s[(k + 3) * NH + j], z3);
            }
            float z = elu_ref((z0 + z1) + (z2 + z3));
            float zo = __shfl_xor_sync(0xffffffffu, z, 1);
            if ((j & 1) == 0) {
                unsigned int u;
                asm("cvt.rn.bf16x2.f32 %0, %1, %2;" : "=r"(u) : "f"(zo), "f"(z));
                g_staged[row * 32 + (j >> 1)] = __uint_as_float(u);
            }
        }
    } else if (blk < TBLK + 4) {
        int arr = blk - TBLK;
        const float* src = (arr < 2) ? w3 : w4;
        int parity = arr & 1;
        int dst = W3A_OFF + arr * 32 * WSTRIDE;
#pragma unroll
        for (int i = t; i < 32 * NH; i += 256) {
            int k = i >> 5, l = i & 31;
            g_staged[dst + l * WSTRIDE + k] = src[k * NH + 2 * l + parity];
        }
    } else {
        if (t < 32) g_staged[TROWS * 32 + t] = 0.0f;
        if (t < NI) {
            int idx = item_index[t];
            float imu = mu_table[idx];
            float ilv = logvar_table[idx];
            g_staged[IFE_OFF + t] = fmaf(eps_item[t], __expf(0.5f * ilv), imu);
            out[O_IMU + t] = imu;
            out[O_ILV + t] = ilv;
        }
    }
}

// ---------------------------------------------------------------------------
// Kernel 2: 14 warps, 2 persons/warp (R13 structure); scalar-FADD unpack;
// eps_ability prefetched in the prologue.
// ---------------------------------------------------------------------------
__global__ __launch_bounds__(NTHR, 1)
void vibo_main_kernel(const float* __restrict__ response,
                      const int*   __restrict__ mask,
                      const float* __restrict__ eps_ability,
                      const float* __restrict__ b3,
                      const float* __restrict__ b4,
                      float* __restrict__ out) {
    extern __shared__ float sm[];
    const int tid = threadIdx.x;
    const int wid  = tid >> 5;
    const int lane = tid & 31;
    const int p0 = blockIdx.x * WPC + wid * 2;
    const int p1 = p0 + 1;
    const int d0 = lane * 2;

    unsigned int smb;
    asm("{ .reg .u64 t; cvta.to.shared.u64 t, %1; cvt.u32.u64 %0, t; }"
        : "=r"(smb) : "l"(sm));
    const unsigned int bar1 = smb + MBAR_OFF * 4;
    const unsigned int bar2 = bar1 + 8;

    // ---- early gmem loads (both persons) + eps prefetch ----
    float4 r0a, r1a, r0b, r1b; int4 m0a, m1a, m0b, m1b;
    float2 epsA = make_float2(0.f, 0.f), epsB = make_float2(0.f, 0.f);
    if (p0 < NP) {
        const float4* rp = (const float4*)(response + p0 * NI);
        const int4*   mp = (const int4*)(mask + p0 * NI);
        r0a = rp[lane * 2]; r1a = rp[lane * 2 + 1];
        m0a = mp[lane * 2]; m1a = mp[lane * 2 + 1];
        if (lane < 16) epsA = *(const float2*)&eps_ability[p0 * NA + d0];
    }
    if (p1 < NP) {
        const float4* rp = (const float4*)(response + p1 * NI);
        const int4*   mp = (const int4*)(mask + p1 * NI);
        r0b = rp[lane * 2]; r1b = rp[lane * 2 + 1];
        m0b = mp[lane * 2]; m1b = mp[lane * 2 + 1];
        if (lane < 16) epsB = *(const float2*)&eps_ability[p1 * NA + d0];
    }

    if (tid == 0) {
        asm volatile("mbarrier.init.shared.b64 [%0], 1;" :: "r"(bar1) : "memory");
        asm volatile("mbarrier.init.shared.b64 [%0], 1;" :: "r"(bar2) : "memory");
    }
    __syncthreads();
    if (tid == 0) {
        asm volatile("mbarrier.arrive.expect_tx.shared.b64 _, [%0], %1;"
                     :: "r"(bar1), "r"((unsigned)TAB_BYTES) : "memory");
        asm volatile("cp.async.bulk.shared::cluster.global.mbarrier::complete_tx::bytes "
                     "[%0], [%1], %2, [%3];"
                     :: "r"(smb), "l"((const void*)g_staged),
                        "r"((unsigned)TAB_BYTES), "r"(bar1) : "memory");
        asm volatile("mbarrier.arrive.expect_tx.shared.b64 _, [%0], %1;"
                     :: "r"(bar2), "r"((unsigned)CHUNK2_BYTES) : "memory");
        asm volatile("cp.async.bulk.shared::cluster.global.mbarrier::complete_tx::bytes "
                     "[%0], [%1], %2, [%3];"
                     :: "r"(smb + TAB_BYTES), "l"((const void*)(g_staged + TAB_WORDS)),
                        "r"((unsigned)CHUNK2_BYTES), "r"(bar2) : "memory");
    }

    // ---- compaction for both persons (overlaps TMA) ----
    unsigned int* cmp0 = (unsigned int*)(sm + CMP_OFF) + (wid * 2) * CMP_STRIDE;
    unsigned int* cmp1 = cmp0 + CMP_STRIDE;
    int tot0 = 0, tot1 = 0;
#pragma unroll
    for (int pp = 0; pp < 2; pp++) {
        int pv = pp ? p1 : p0;
        if (pv >= NP) continue;
        float4 rA = pp ? r0b : r0a, rB = pp ? r1b : r1a;
        int4   mA = pp ? m0b : m0a, mB = pp ? m1b : m1a;
        float rv[8] = {rA.x, rA.y, rA.z, rA.w, rB.x, rB.y, rB.z, rB.w};
        int   mv[8] = {mA.x, mA.y, mA.z, mA.w, mB.x, mB.y, mB.z, mB.w};
        int cnt = 0;
#pragma unroll
        for (int j = 0; j < 8; j++) cnt += (mv[j] != 0);
        int off = cnt;
#pragma unroll
        for (int d = 1; d < 32; d <<= 1) {
            int t = __shfl_up_sync(0xffffffffu, off, d);
            if (lane >= d) off += t;
        }
        int tot = __shfl_sync(0xffffffffu, off, 31);
        off -= cnt;
        unsigned int* cc = pp ? cmp1 : cmp0;
        int pos = off;
#pragma unroll
        for (int j = 0; j < 8; j++) {
            if (mv[j]) {
                int b = __float2int_rn(rv[j] * (float)NBINS);
                if (b < 0) b = 0;
                if (b > NBINS) b = NBINS;
                cc[pos++] = (unsigned int)(b << 7);
            }
        }
        if (pp) tot1 = tot; else tot0 = tot;
    }
    int tmax = max(tot0, tot1);
    int totalp = (tmax + 3) & ~3;
    for (int t = tot0 + lane; t < totalp + 4; t += 32) cmp0[t] = PADOFF;
    for (int t = tot1 + lane; t < totalp + 4; t += 32) cmp1[t] = PADOFF;
    __syncwarp();

    mbar_wait(bar1);
    if (p0 >= NP) return;

    // ---- NN accumulate, both persons, prefetched offsets, scalar FADDs ----
    const char* tb = (const char*)sm + lane * 4;
    const uint4* c0 = (const uint4*)cmp0;
    const uint4* c1 = (const uint4*)cmp1;
    float aL0 = 0.f, aH0 = 0.f, aL1 = 0.f, aH1 = 0.f;   // person A (2 chains)
    float bL0 = 0.f, bH0 = 0.f, bL1 = 0.f, bH1 = 0.f;   // person B
    const int n4 = totalp >> 2;
    uint4 oA4 = c0[0];
    uint4 oB4 = c1[0];
#pragma unroll 2
    for (int i = 0; i < n4; i++) {
        uint4 nA = c0[i + 1];
        uint4 nB = c1[i + 1];
        unsigned int vA0 = *(const unsigned int*)(tb + oA4.x);
        unsigned int vA1 = *(const unsigned int*)(tb + oA4.y);
        unsigned int vA2 = *(const unsigned int*)(tb + oA4.z);
        unsigned int vA3 = *(const unsigned int*)(tb + oA4.w);
        unsigned int vB0 = *(const unsigned int*)(tb + oB4.x);
        unsigned int vB1 = *(const unsigned int*)(tb + oB4.y);
        unsigned int vB2 = *(const unsigned int*)(tb + oB4.z);
        unsigned int vB3 = *(const unsigned int*)(tb + oB4.w);
        addbf_s(aL0, aH0, vA0); addbf_s(aL1, aH1, vA1);
        addbf_s(bL0, bH0, vB0); addbf_s(bL1, bH1, vB1);
        addbf_s(aL0, aH0, vA2); addbf_s(aL1, aH1, vA3);
        addbf_s(bL0, bH0, vB2); addbf_s(bL1, bH1, vB3);
        oA4 = nA; oB4 = nB;
    }
    float h0x = aL0 + aL1, h0y = aH0 + aH1;
    float h1x = bL0 + bL1, h1y = bH0 + bH1;
    float inv0 = 1.0f / fmaxf((float)tot0, 1.0f);
    float inv1 = 1.0f / fmaxf((float)tot1, 1.0f);

    float* buf0 = sm + BUF_OFF + (wid * 2) * NH;
    float* buf1 = buf0 + NH;
    buf0[d0] = h0x * inv0; buf0[d0 + 1] = h0y * inv0;
    buf1[d0] = h1x * inv1; buf1[d0 + 1] = h1y * inv1;
    __syncwarp();

    mbar_wait(bar2);

    // ---- layer 3 (weights shared across both persons) ----
    const ulonglong2* hb0 = (const ulonglong2*)buf0;
    const ulonglong2* hb1 = (const ulonglong2*)buf1;
    const ulonglong2* wa3 = (const ulonglong2*)(sm + W3A_OFF + lane * WSTRIDE);
    const ulonglong2* wb3 = (const ulonglong2*)(sm + W3B_OFF + lane * WSTRIDE);
    unsigned long long zP0, zP1, zQ0, zQ1;
    {
        float bz = b3[d0], bz1 = b3[d0 + 1], zf = 0.0f;
        asm("mov.b64 %0, {%1, %2};" : "=l"(zP0) : "f"(bz),  "f"(zf));
        asm("mov.b64 %0, {%1, %2};" : "=l"(zP1) : "f"(bz1), "f"(zf));
        zQ0 = zP0; zQ1 = zP1;
    }
#pragma unroll
    for (int k4 = 0; k4 < NH / 4; k4++) {
        ulonglong2 hA = hb0[k4];
        ulonglong2 hB = hb1[k4];
        ulonglong2 wa = wa3[k4];
        ulonglong2 wb = wb3[k4];
        fma2(zP0, hA.x, wa.x); fma2(zP0, hA.y, wa.y);
        fma2(zP1, hA.x, wb.x); fma2(zP1, hA.y, wb.y);
        fma2(zQ0, hB.x, wa.x); fma2(zQ0, hB.y, wa.y);
        fma2(zQ1, hB.x, wb.x); fma2(zQ1, hB.y, wb.y);
    }
    float s0, s1, s2, s3;
    asm("mov.b64 {%0, %1}, %2;" : "=f"(s0), "=f"(s1) : "l"(zP0));
    asm("mov.b64 {%0, %1}, %2;" : "=f"(s2), "=f"(s3) : "l"(zP1));
    float uA0 = elu_fast(s0 + s1), uA1 = elu_fast(s2 + s3);
    asm("mov.b64 {%0, %1}, %2;" : "=f"(s0), "=f"(s1) : "l"(zQ0));
    asm("mov.b64 {%0, %1}, %2;" : "=f"(s2), "=f"(s3) : "l"(zQ1));
    float uB0 = elu_fast(s0 + s1), uB1 = elu_fast(s2 + s3);
    __syncwarp();
    buf0[d0] = uA0; buf0[d0 + 1] = uA1;
    buf1[d0] = uB0; buf1[d0 + 1] = uB1;
    __syncwarp();

    // ---- layer 4 ----
    const ulonglong2* wa4 = (const ulonglong2*)(sm + W4A_OFF + lane * WSTRIDE);
    const ulonglong2* wb4 = (const ulonglong2*)(sm + W4B_OFF + lane * WSTRIDE);
    {
        float bz = b4[d0], bz1 = b4[d0 + 1], zf = 0.0f;
        asm("mov.b64 %0, {%1, %2};" : "=l"(zP0) : "f"(bz),  "f"(zf));
        asm("mov.b64 %0, {%1, %2};" : "=l"(zP1) : "f"(bz1), "f"(zf));
        zQ0 = zP0; zQ1 = zP1;
    }
#pragma unroll
    for (int k4 = 0; k4 < NH / 4; k4++) {
        ulonglong2 hA = hb0[k4];
        ulonglong2 hB = hb1[k4];
        ulonglong2 wa = wa4[k4];
        ulonglong2 wb = wb4[k4];
        fma2(zP0, hA.x, wa.x); fma2(zP0, hA.y, wa.y);
        fma2(zP1, hA.x, wb.x); fma2(zP1, hA.y, wb.y);
        fma2(zQ0, hB.x, wa.x); fma2(zQ0, hB.y, wa.y);
        fma2(zQ1, hB.x, wb.x); fma2(zQ1, hB.y, wb.y);
    }
    float oA0, oA1, oB0, oB1;
    asm("mov.b64 {%0, %1}, %2;" : "=f"(s0), "=f"(s1) : "l"(zP0));
    asm("mov.b64 {%0, %1}, %2;" : "=f"(s2), "=f"(s3) : "l"(zP1));
    oA0 = s0 + s1; oA1 = s2 + s3;
    asm("mov.b64 {%0, %1}, %2;" : "=f"(s0), "=f"(s1) : "l"(zQ0));
    asm("mov.b64 {%0, %1}, %2;" : "=f"(s2), "=f"(s3) : "l"(zQ1));
    oB0 = s0 + s1; oB1 = s2 + s3;

    // ---- epilogue per person ----
#pragma unroll
    for (int pp = 0; pp < 2; pp++) {
        int p = pp ? p1 : p0;
        if (p >= NP) break;
        float o0 = pp ? oB0 : oA0;
        float o1 = pp ? oB1 : oA1;
        float2 eps = pp ? epsB : epsA;
        float2 ov = make_float2(o0, o1);
        if (lane < 16) *(float2*)&out[O_AMU + p * NA + d0] = ov;
        else           *(float2*)&out[O_ALV + p * NA + (d0 - NA)] = ov;

        float lv0 = __shfl_down_sync(0xffffffffu, o0, 16);
        float lv1 = __shfl_down_sync(0xffffffffu, o1, 16);
        float term = 0.0f;
        if (lane < 16) {
            term = o0 + eps.x * __expf(0.5f * lv0)
                 + o1 + eps.y * __expf(0.5f * lv1);
        }
#pragma unroll
        for (int w = 16; w > 0; w >>= 1)
            term += __shfl_xor_sync(0xffffffffu, term, w);
        float asum = term;

        const float4* ifp = (const float4*)(sm + IFE_OFF + lane * 8);
        float4* orow = (float4*)(out + p * NI + lane * 8);
#pragma unroll
        for (int v = 0; v < 2; v++) {
            float4 f = ifp[v];
            float4 r;
            r.x = __fdividef(1.0f, 1.0f + __expf(-(asum + f.x)));
            r.y = __fdividef(1.0f, 1.0f + __expf(-(asum + f.y)));
            r.z = __fdividef(1.0f, 1.0f + __expf(-(asum + f.z)));
            r.w = __fdividef(1.0f, 1.0f + __expf(-(asum + f.w)));
            orow[v] = r;
        }
    }
}

// ---------------------------------------------------------------------------
extern "C" void kernel_launch(void* const* d_in, const int* in_sizes, int n_in,
                              void* d_out, int out_size) {
    const float* response     = (const float*)d_in[0];
    const int*   mask         = (const int*)  d_in[1];
    const int*   item_index   = (const int*)  d_in[2];
    const float* eps_ability  = (const float*)d_in[3];
    const float* eps_item     = (const float*)d_in[4];
    const float* w1           = (const float*)d_in[5];
    const float* b1           = (const float*)d_in[6];
    const float* w2           = (const float*)d_in[7];
    const float* b2           = (const float*)d_in[8];
    const float* w3           = (const float*)d_in[9];
    const float* b3           = (const float*)d_in[10];
    const float* w4           = (const float*)d_in[11];
    const float* b4           = (const float*)d_in[12];
    const float* mu_table     = (const float*)d_in[13];
    const float* logvar_table = (const float*)d_in[14];
    float* out = (float*)d_out;

    cudaFuncSetAttribute(vibo_main_kernel,
                         cudaFuncAttributeMaxDynamicSharedMemorySize, SMEM_BYTES);

    build_all_kernel<<<TBLK + 5, 256>>>(w1, b1, w2, b2, w3, w4,
                                        item_index, eps_item,
                                        mu_table, logvar_table, out);

    vibo_main_kernel<<<GRID, NTHR, SMEM_BYTES>>>(response, mask,
                                                 eps_ability, b3, b4, out);
}